// round 1
// baseline (speedup 1.0000x reference)
#include <cuda_runtime.h>
#include <math.h>

// Problem constants
#define NB   32
#define C    256
#define CI   64
#define L    6
#define T    64
#define V    50
#define K    3
#define EPSV 1e-5f

// x strides (N,C,L,T,V): v=1, t=50, l=3200, c=19200, n=4915200
#define XT_ELEMS  (NB*C*L*V)      // 2,457,600
#define Y_ELEMS   (NB*CI*L*V)     // 614,400
#define OUT_ELEMS (NB*C*T*V)      // 26,214,400

// Scratch (device globals — no allocations allowed)
__device__ float g_xt[XT_ELEMS];
__device__ float g_y[Y_ELEMS];
__device__ float g_stat1[2*CI];     // mean | rstd
__device__ float g_xs[NB*CI*L];     // [n][d][l]
__device__ float g_epre[NB*CI*L*K]; // [n][d][l][k]
__device__ float g_stat2[2*CI];
__device__ float g_att[NB*C*L];     // [n][c][l]

__constant__ int c_off[7] = {0, 6, 20, 42, 62, 78, 94};
__constant__ int c_layers[94] = {
    1, 0, 20, 26, 25, 45,
    0, 20, 12, 16, 2, 4, 8, 25, 45, 37, 41, 27, 29, 33,
    12, 16, 2, 4, 8, 13, 17, 3, 5, 9, 3, 28, 37, 41, 27, 29, 33, 38, 42, 28, 30, 34,
    13, 17, 3, 5, 9, 14, 18, 6, 10, 3, 28, 38, 42, 28, 30, 34, 39, 43, 31, 35,
    14, 18, 6, 10, 15, 19, 7, 11, 39, 43, 31, 35, 40, 44, 32, 36,
    15, 19, 7, 11, 21, 22, 23, 24, 40, 44, 32, 36, 46, 47, 48, 49
};

// ---------------------------------------------------------------------------
// K1: x_t[n,c,l,v] = max_t x[n,c,l,t,v]   (reads 629MB, writes 9.8MB)
// ---------------------------------------------------------------------------
__global__ void __launch_bounds__(256) k_maxT(const float* __restrict__ x) {
    int idx = blockIdx.x * 256 + threadIdx.x;           // over XT_ELEMS
    if (idx >= XT_ELEMS) return;
    int v   = idx % V;
    int ncl = idx / V;
    const float* p = x + (size_t)ncl * (T * V) + v;
    float m0 = -INFINITY, m1 = -INFINITY, m2 = -INFINITY, m3 = -INFINITY;
#pragma unroll
    for (int t = 0; t < T; t += 4) {
        m0 = fmaxf(m0, __ldg(p + (t + 0) * V));
        m1 = fmaxf(m1, __ldg(p + (t + 1) * V));
        m2 = fmaxf(m2, __ldg(p + (t + 2) * V));
        m3 = fmaxf(m3, __ldg(p + (t + 3) * V));
    }
    g_xt[idx] = fmaxf(fmaxf(m0, m1), fmaxf(m2, m3));
}

// ---------------------------------------------------------------------------
// K2: y[n,d,l,v] = sum_c W_down[d,c] * xt[n,c,l,v] + b_down[d]
// One block per (n,l). 200 active threads: v = tid%50, dg = tid/50 (d = dg*16+i)
// ---------------------------------------------------------------------------
__global__ void __launch_bounds__(256) k_down(const float* __restrict__ Wd,
                                              const float* __restrict__ bd) {
    int n = blockIdx.x / L;
    int l = blockIdx.x % L;
    __shared__ float sx[128 * V];   // 25.6 KB chunk of xt
    int tid = threadIdx.x;
    int v = tid % V;
    int dg = tid / V;               // 0..3 valid (tid<200)
    float acc[16];
#pragma unroll
    for (int i = 0; i < 16; i++) acc[i] = 0.f;

    for (int chunk = 0; chunk < 2; chunk++) {
        int cbase = chunk * 128;
        for (int j = tid; j < 128 * V; j += 256) {
            int cc = j / V, vv = j % V;
            sx[j] = g_xt[(n * C + cbase + cc) * (L * V) + l * V + vv];
        }
        __syncthreads();
        if (tid < 200) {
            for (int cc = 0; cc < 128; cc++) {
                float xv = sx[cc * V + v];
#pragma unroll
                for (int i = 0; i < 16; i++)
                    acc[i] += __ldg(&Wd[(dg * 16 + i) * C + cbase + cc]) * xv;
            }
        }
        __syncthreads();
    }
    if (tid < 200) {
#pragma unroll
        for (int i = 0; i < 16; i++) {
            int d = dg * 16 + i;
            g_y[((n * CI + d) * L + l) * V + v] = acc[i] + __ldg(&bd[d]);
        }
    }
}

// ---------------------------------------------------------------------------
// K3: BN1 stats per channel d over (n,l,v) : 9600 elems. One block per d.
// ---------------------------------------------------------------------------
__global__ void __launch_bounds__(256) k_bn1() {
    int d = blockIdx.x;
    __shared__ float s1[256], s2[256];
    float sum = 0.f, sq = 0.f;
    for (int i = threadIdx.x; i < NB * L * V; i += 256) {
        int n = i / (L * V), r = i % (L * V);
        float yv = g_y[n * (CI * L * V) + d * (L * V) + r];
        sum += yv; sq += yv * yv;
    }
    s1[threadIdx.x] = sum; s2[threadIdx.x] = sq;
    __syncthreads();
    for (int st = 128; st > 0; st >>= 1) {
        if (threadIdx.x < st) { s1[threadIdx.x] += s1[threadIdx.x + st];
                                s2[threadIdx.x] += s2[threadIdx.x + st]; }
        __syncthreads();
    }
    if (threadIdx.x == 0) {
        float cnt = (float)(NB * L * V);
        float mean = s1[0] / cnt;
        float var  = s2[0] / cnt - mean * mean;
        g_stat1[d]      = mean;
        g_stat1[CI + d] = rsqrtf(var + EPSV);
    }
}

// ---------------------------------------------------------------------------
// K4: xs[n,d,l] = mean over LAYERS[l] of relu(bn1(y)). Block per (n,l), 64 thr.
// ---------------------------------------------------------------------------
__global__ void __launch_bounds__(64) k_xs(const float* __restrict__ g1,
                                           const float* __restrict__ b1) {
    int n = blockIdx.x / L;
    int l = blockIdx.x % L;
    int d = threadIdx.x;
    float mean = g_stat1[d], rstd = g_stat1[CI + d];
    float gm = __ldg(&g1[d]), bt = __ldg(&b1[d]);
    int base = (n * CI + d) * (L * V) + l * V;
    int o0 = c_off[l], o1 = c_off[l + 1];
    float s = 0.f;
    for (int j = o0; j < o1; j++) {
        float yv = (g_y[base + c_layers[j]] - mean) * rstd * gm + bt;
        s += fmaxf(yv, 0.f);
    }
    g_xs[(n * CI + d) * L + l] = s / (float)(o1 - o0);
}

// ---------------------------------------------------------------------------
// K5: per-n graph: pd -> topk -> edge features -> W_edge GEMM -> e_pre
// Block per n, 64 threads (thread = channel d).
// ---------------------------------------------------------------------------
__global__ void __launch_bounds__(64) k_graph(const float* __restrict__ We) {
    int n = blockIdx.x;
    int d = threadIdx.x;
    __shared__ float sxs[CI * L];     // [c][l]
    __shared__ float sxx[L];
    __shared__ float spd[L * L];
    __shared__ int   sidx[L * K];

#pragma unroll
    for (int l = 0; l < L; l++)
        sxs[d * L + l] = g_xs[(n * CI + d) * L + l];
    __syncthreads();

    if (d < L) {
        float s = 0.f;
        for (int c = 0; c < CI; c++) { float v = sxs[c * L + d]; s += v * v; }
        sxx[d] = s;
    }
    __syncthreads();
    if (d < L * L) {
        int l = d / L, m = d % L;
        float s = 0.f;
        for (int c = 0; c < CI; c++) s += sxs[c * L + l] * sxs[c * L + m];
        spd[d] = 2.f * s - sxx[l] - sxx[m];
    }
    __syncthreads();
    if (d < L) {
        int taken = 0;
        for (int k = 0; k < K; k++) {
            int best = -1; float bv = -INFINITY;
            for (int m = 0; m < L; m++) {
                if ((taken >> m) & 1) continue;
                float pv = spd[d * L + m];
                if (pv > bv) { bv = pv; best = m; }
            }
            taken |= (1 << best);
            sidx[d * K + k] = best;
        }
    }
    __syncthreads();

    // e_pre[n,d,l,k] = sum_c We[d,c]*(xs[c,idx]-xs[c,l]) + We[d,64+c]*xs[c,l]
    float acc[L * K];
#pragma unroll
    for (int j = 0; j < L * K; j++) acc[j] = 0.f;
    for (int c = 0; c < CI; c++) {
        float wa = __ldg(&We[d * (2 * CI) + c]);
        float wb = __ldg(&We[d * (2 * CI) + CI + c]);
#pragma unroll
        for (int l = 0; l < L; l++) {
            float ctr = sxs[c * L + l];
#pragma unroll
            for (int k = 0; k < K; k++) {
                float ft = sxs[c * L + sidx[l * K + k]];
                acc[l * K + k] += wa * (ft - ctr) + wb * ctr;
            }
        }
    }
#pragma unroll
    for (int l = 0; l < L; l++)
#pragma unroll
        for (int k = 0; k < K; k++)
            g_epre[((n * CI + d) * L + l) * K + k] = acc[l * K + k];
}

// ---------------------------------------------------------------------------
// K6: BN2 stats per channel over (n,l,k): 576 elems. Block per d, 64 thr.
// ---------------------------------------------------------------------------
__global__ void __launch_bounds__(64) k_bn2() {
    int d = blockIdx.x;
    __shared__ float s1[64], s2[64];
    float sum = 0.f, sq = 0.f;
    for (int i = threadIdx.x; i < NB * L * K; i += 64) {
        int n = i / (L * K), r = i % (L * K);
        float e = g_epre[n * (CI * L * K) + d * (L * K) + r];
        sum += e; sq += e * e;
    }
    s1[threadIdx.x] = sum; s2[threadIdx.x] = sq;
    __syncthreads();
    for (int st = 32; st > 0; st >>= 1) {
        if (threadIdx.x < st) { s1[threadIdx.x] += s1[threadIdx.x + st];
                                s2[threadIdx.x] += s2[threadIdx.x + st]; }
        __syncthreads();
    }
    if (threadIdx.x == 0) {
        float cnt = (float)(NB * L * K);
        float mean = s1[0] / cnt;
        float var  = s2[0] / cnt - mean * mean;
        g_stat2[d]      = mean;
        g_stat2[CI + d] = rsqrtf(var + EPSV);
    }
}

// ---------------------------------------------------------------------------
// K7: e = max_k lrelu(bn2(e_pre)); att = sigmoid(W_agg @ e + b_agg)
// Block per n, 256 threads.
// ---------------------------------------------------------------------------
__global__ void __launch_bounds__(256) k_att(const float* __restrict__ g2,
                                             const float* __restrict__ b2,
                                             const float* __restrict__ Wa,
                                             const float* __restrict__ ba) {
    int n = blockIdx.x;
    int tid = threadIdx.x;
    __shared__ float se[CI * L];      // [d][l]
    if (tid < CI) {
        int d = tid;
        float mean = g_stat2[d], rstd = g_stat2[CI + d];
        float gm = __ldg(&g2[d]), bt = __ldg(&b2[d]);
#pragma unroll
        for (int l = 0; l < L; l++) {
            float mx = -INFINITY;
#pragma unroll
            for (int k = 0; k < K; k++) {
                float e = (g_epre[((n * CI + d) * L + l) * K + k] - mean) * rstd * gm + bt;
                e = (e >= 0.f) ? e : 0.2f * e;
                mx = fmaxf(mx, e);
            }
            se[d * L + l] = mx;
        }
    }
    __syncthreads();
    int cch = tid;                    // 0..255
    float acc[L];
#pragma unroll
    for (int l = 0; l < L; l++) acc[l] = 0.f;
    for (int d = 0; d < CI; d++) {
        float w = __ldg(&Wa[cch * CI + d]);
#pragma unroll
        for (int l = 0; l < L; l++) acc[l] += w * se[d * L + l];
    }
    float bb = __ldg(&ba[cch]);
#pragma unroll
    for (int l = 0; l < L; l++) {
        float a = acc[l] + bb;
        g_att[(n * C + cch) * L + l] = 1.f / (1.f + expf(-a));
    }
}

// ---------------------------------------------------------------------------
// K8: out[n,c,t,v] = sum_l x[n,c,l,t,v] * att[n,c,l]  (reads 629MB, writes 105MB)
// ---------------------------------------------------------------------------
__global__ void __launch_bounds__(256) k_out(const float* __restrict__ x,
                                             float* __restrict__ out) {
    int idx = blockIdx.x * 256 + threadIdx.x;           // over OUT_ELEMS
    if (idx >= OUT_ELEMS) return;
    int tv = idx % (T * V);
    int nc = idx / (T * V);
    const float* px = x + (size_t)nc * (L * T * V) + tv;
    float a0 = __ldg(&g_att[nc * L + 0]);
    float a1 = __ldg(&g_att[nc * L + 1]);
    float a2 = __ldg(&g_att[nc * L + 2]);
    float a3 = __ldg(&g_att[nc * L + 3]);
    float a4 = __ldg(&g_att[nc * L + 4]);
    float a5 = __ldg(&g_att[nc * L + 5]);
    float s = a0 * __ldg(px)
            + a1 * __ldg(px + 1 * T * V)
            + a2 * __ldg(px + 2 * T * V)
            + a3 * __ldg(px + 3 * T * V)
            + a4 * __ldg(px + 4 * T * V)
            + a5 * __ldg(px + 5 * T * V);
    out[idx] = s;
}

// ---------------------------------------------------------------------------
extern "C" void kernel_launch(void* const* d_in, const int* in_sizes, int n_in,
                              void* d_out, int out_size) {
    const float* x      = (const float*)d_in[0];
    const float* W_down = (const float*)d_in[1];
    const float* b_down = (const float*)d_in[2];
    const float* gamma1 = (const float*)d_in[3];
    const float* beta1  = (const float*)d_in[4];
    const float* W_edge = (const float*)d_in[5];
    const float* gamma2 = (const float*)d_in[6];
    const float* beta2  = (const float*)d_in[7];
    const float* W_agg  = (const float*)d_in[8];
    const float* b_agg  = (const float*)d_in[9];
    float* out = (float*)d_out;

    k_maxT<<<(XT_ELEMS + 255) / 256, 256>>>(x);
    k_down<<<NB * L, 256>>>(W_down, b_down);
    k_bn1<<<CI, 256>>>();
    k_xs<<<NB * L, 64>>>(gamma1, beta1);
    k_graph<<<NB, 64>>>(W_edge);
    k_bn2<<<CI, 64>>>();
    k_att<<<NB, 256>>>(gamma2, beta2, W_agg, b_agg);
    k_out<<<(OUT_ELEMS + 255) / 256, 256>>>(x, out);
}